// round 1
// baseline (speedup 1.0000x reference)
#include <cuda_runtime.h>
#include <math.h>

#define NUSERS 100000
#define NITEMS 50000
#define NFEATS 512
#define DIM 32
#define ESOC 3200000
#define EUI 3200000
#define NPAIRS 1000000

// ---------------- scratch (device globals; no allocs allowed) ----------------
__device__ double g_red[8];            // [0,1]=uf sum/sq [2,3]=itf [4,5]=usig [6,7]=isig
__device__ float  g_colsum[DIM];       // column sums of wr_w
__device__ float  g_user_sig[NUSERS * DIM];   // raw GEMM -> sigmoid (in place)
__device__ float  g_item_sig[NITEMS * DIM];
__device__ float  g_user_fus[NUSERS * DIM];
__device__ float  g_item_fus[NITEMS * DIM];
__device__ float  g_h1[NUSERS * DIM];
__device__ float  g_last[NUSERS * DIM];       // item_consumed + h2 accumulate here

// ---------------- init: zero accumulators ----------------
__global__ void k_init() {
    int i = blockIdx.x * blockDim.x + threadIdx.x;   // grid covers NUSERS*DIM/4
    float4 z = make_float4(0.f, 0.f, 0.f, 0.f);
    const int n4 = NUSERS * DIM / 4;
    if (i < n4) {
        reinterpret_cast<float4*>(g_h1)[i]   = z;
        reinterpret_cast<float4*>(g_last)[i] = z;
    }
    if (i < 8) g_red[i] = 0.0;
}

// ---------------- column sums of W (512x32) ----------------
__global__ void k_colsum(const float* __restrict__ W) {
    __shared__ float s[8][DIM];
    int c = threadIdx.x & 31;
    int g = threadIdx.x >> 5;      // 256 threads -> 8 groups
    float acc = 0.f;
    for (int k = g; k < NFEATS; k += 8) acc += W[k * DIM + c];
    s[g][c] = acc;
    __syncthreads();
    if (g == 0) {
        float t = 0.f;
#pragma unroll
        for (int j = 0; j < 8; j++) t += s[j][c];
        g_colsum[c] = t;
    }
}

// ---------------- GEMM: raw = F @ W, fused feature-stats reduction ----------------
// Block: 128 threads, 64 rows x 32 cols, per-thread 4x4 register tile.
__global__ __launch_bounds__(128) void k_gemm(const float* __restrict__ F,
                                              const float* __restrict__ W,
                                              int M, int redIdx, int outSel) {
    __shared__ float sF[64][33];
    __shared__ float sW[32][36];
    float* __restrict__ out = outSel ? g_item_sig : g_user_sig;

    int t  = threadIdx.x;
    int tc = t & 7;        // 8 col-groups (4 cols each)
    int tr = t >> 3;       // 16 row-groups (4 rows each)
    int row0 = blockIdx.x * 64;

    float acc[4][4] = {};
    double lsum = 0.0, lsq = 0.0;

    for (int kt = 0; kt < NFEATS / 32; ++kt) {
        int k0 = kt * 32;
        // load feature tile: 64 rows x 32 k = 512 float4, 4 per thread
#pragma unroll
        for (int i = 0; i < 4; ++i) {
            int fi = t + i * 128;
            int r = fi >> 3, kq = fi & 7;
            float4 v = make_float4(0.f, 0.f, 0.f, 0.f);
            int grow = row0 + r;
            if (grow < M)
                v = *reinterpret_cast<const float4*>(&F[(size_t)grow * NFEATS + k0 + kq * 4]);
            sF[r][kq * 4 + 0] = v.x; sF[r][kq * 4 + 1] = v.y;
            sF[r][kq * 4 + 2] = v.z; sF[r][kq * 4 + 3] = v.w;
            lsum += (double)v.x + (double)v.y + (double)v.z + (double)v.w;
            lsq  += (double)v.x * v.x + (double)v.y * v.y
                  + (double)v.z * v.z + (double)v.w * v.w;
        }
        // load W tile: 32 k x 32 cols = 256 float4, 2 per thread
#pragma unroll
        for (int i = 0; i < 2; ++i) {
            int fi = t + i * 128;
            int kr = fi >> 3, kq = fi & 7;
            float4 w = *reinterpret_cast<const float4*>(&W[(size_t)(k0 + kr) * DIM + kq * 4]);
            sW[kr][kq * 4 + 0] = w.x; sW[kr][kq * 4 + 1] = w.y;
            sW[kr][kq * 4 + 2] = w.z; sW[kr][kq * 4 + 3] = w.w;
        }
        __syncthreads();
#pragma unroll
        for (int k = 0; k < 32; ++k) {
            float4 w = *reinterpret_cast<float4*>(&sW[k][tc * 4]);
            float f0 = sF[tr * 4 + 0][k];
            float f1 = sF[tr * 4 + 1][k];
            float f2 = sF[tr * 4 + 2][k];
            float f3 = sF[tr * 4 + 3][k];
            acc[0][0] += f0 * w.x; acc[0][1] += f0 * w.y; acc[0][2] += f0 * w.z; acc[0][3] += f0 * w.w;
            acc[1][0] += f1 * w.x; acc[1][1] += f1 * w.y; acc[1][2] += f1 * w.z; acc[1][3] += f1 * w.w;
            acc[2][0] += f2 * w.x; acc[2][1] += f2 * w.y; acc[2][2] += f2 * w.z; acc[2][3] += f2 * w.w;
            acc[3][0] += f3 * w.x; acc[3][1] += f3 * w.y; acc[3][2] += f3 * w.z; acc[3][3] += f3 * w.w;
        }
        __syncthreads();
    }

    // reduce feature stats: warp shuffle + smem + atomic
#pragma unroll
    for (int o = 16; o; o >>= 1) {
        lsum += __shfl_down_sync(0xffffffffu, lsum, o);
        lsq  += __shfl_down_sync(0xffffffffu, lsq, o);
    }
    __shared__ double sred[4][2];
    int wid = t >> 5, lane = t & 31;
    if (lane == 0) { sred[wid][0] = lsum; sred[wid][1] = lsq; }
    __syncthreads();
    if (t == 0) {
        double a = 0.0, b = 0.0;
#pragma unroll
        for (int j = 0; j < 4; j++) { a += sred[j][0]; b += sred[j][1]; }
        atomicAdd(&g_red[redIdx], a);
        atomicAdd(&g_red[redIdx + 1], b);
    }

    // store raw result
#pragma unroll
    for (int i = 0; i < 4; ++i) {
        int grow = row0 + tr * 4 + i;
        if (grow < M) {
            float4 o4 = make_float4(acc[i][0], acc[i][1], acc[i][2], acc[i][3]);
            *reinterpret_cast<float4*>(&out[(size_t)grow * DIM + tc * 4]) = o4;
        }
    }
}

// ---------------- epilogue: normalize-fold + sigmoid, fused sig-stats ----------------
__global__ void k_epi(const float* __restrict__ b, int n, double Nfeat,
                      int si, int so, int sel) {
    float* __restrict__ sig = sel ? g_item_sig : g_user_sig;
    double fsum = g_red[si], fsq = g_red[si + 1];
    double mean = fsum / Nfeat;
    double var  = (fsq - fsum * fsum / Nfeat) / (Nfeat - 1.0);
    float inv_s = (float)(1.0 / sqrt(var));
    float mis   = (float)mean * inv_s;

    int i = blockIdx.x * blockDim.x + threadIdx.x;
    double lsum = 0.0, lsq = 0.0;
    if (i < n) {
        int j = i & (DIM - 1);
        float x = sig[i] * inv_s + b[j] - mis * g_colsum[j];
        float v = 1.f / (1.f + expf(-x));
        sig[i] = v;
        lsum = v;
        lsq  = (double)v * v;
    }
#pragma unroll
    for (int o = 16; o; o >>= 1) {
        lsum += __shfl_down_sync(0xffffffffu, lsum, o);
        lsq  += __shfl_down_sync(0xffffffffu, lsq, o);
    }
    __shared__ double sred[8][2];
    int wid = threadIdx.x >> 5, lane = threadIdx.x & 31;
    if (lane == 0) { sred[wid][0] = lsum; sred[wid][1] = lsq; }
    __syncthreads();
    if (threadIdx.x == 0) {
        double a = 0.0, c = 0.0;
#pragma unroll
        for (int j = 0; j < 8; j++) { a += sred[j][0]; c += sred[j][1]; }
        atomicAdd(&g_red[so], a);
        atomicAdd(&g_red[so + 1], c);
    }
}

// ---------------- fusion: (sig - m)/s + embedding ----------------
__global__ void k_fusion(const float* __restrict__ emb, int n, int si, int sel) {
    const float* __restrict__ sig = sel ? g_item_sig : g_user_sig;
    float* __restrict__ fus = sel ? g_item_fus : g_user_fus;
    double s0 = g_red[si], s1 = g_red[si + 1];
    double N = (double)n;
    double mean = s0 / N;
    double var  = (s1 - s0 * s0 / N) / (N - 1.0);
    float inv = (float)(1.0 / sqrt(var));
    float m   = (float)mean;
    int i = blockIdx.x * blockDim.x + threadIdx.x;
    if (i < n) fus[i] = (sig[i] - m) * inv + emb[i];
}

// ---------------- SpMM: scatter atomic, 8 threads/edge, v4 reductions ----------------
__global__ void k_spmm(const int* __restrict__ rows, const int* __restrict__ cols,
                       const float* __restrict__ vals, int nE, int selX, int selOut) {
    const float* __restrict__ X =
        (selX == 0) ? g_item_fus : (selX == 1) ? g_user_fus : g_h1;
    float* __restrict__ OUT = selOut ? g_h1 : g_last;

    int tid = blockIdx.x * blockDim.x + threadIdx.x;
    int e = tid >> 3, sub = tid & 7;
    if (e >= nE) return;
    int r = rows[e];
    int c = cols[e];
    float v = vals[e];
    float4 x = *reinterpret_cast<const float4*>(&X[(size_t)c * DIM + sub * 4]);
    float4 y = make_float4(x.x * v, x.y * v, x.z * v, x.w * v);
    float* p = &OUT[(size_t)r * DIM + sub * 4];
    asm volatile("red.global.add.v4.f32 [%0], {%1,%2,%3,%4};"
                 :: "l"(p), "f"(y.x), "f"(y.y), "f"(y.z), "f"(y.w)
                 : "memory");
}

// ---------------- prediction: 8 threads/pair ----------------
__global__ void k_pred(const int* __restrict__ ui, const int* __restrict__ ii,
                       float* __restrict__ out, int out_size) {
    int tid = blockIdx.x * blockDim.x + threadIdx.x;
    int p = tid >> 3, sub = tid & 7;
    if (p >= NPAIRS) return;
    int u  = ui[p];
    int it = ii[p];
    float4 a = *reinterpret_cast<const float4*>(&g_last[(size_t)u * DIM + sub * 4]);
    float4 b = *reinterpret_cast<const float4*>(&g_item_fus[(size_t)it * DIM + sub * 4]);
    float d = a.x * b.x + a.y * b.y + a.z * b.z + a.w * b.w;
#pragma unroll
    for (int o = 4; o; o >>= 1) d += __shfl_down_sync(0xffffffffu, d, o, 8);
    if (sub == 0) {
        if (p < out_size) out[p] = d;
        if (NPAIRS + p < out_size) out[NPAIRS + p] = 1.f / (1.f + expf(-d));
    }
}

// ---------------- launch ----------------
extern "C" void kernel_launch(void* const* d_in, const int* in_sizes, int n_in,
                              void* d_out, int out_size) {
    const float* uf    = (const float*)d_in[0];
    const float* itf   = (const float*)d_in[1];
    const float* uemb  = (const float*)d_in[2];
    const float* iemb  = (const float*)d_in[3];
    const float* wr_w  = (const float*)d_in[4];
    const float* wr_b  = (const float*)d_in[5];
    const int*   srows = (const int*)d_in[6];
    const int*   scols = (const int*)d_in[7];
    const float* svals = (const float*)d_in[8];
    const int*   urows = (const int*)d_in[9];
    const int*   ucols = (const int*)d_in[10];
    const float* uvals = (const float*)d_in[11];
    const int*   uidx  = (const int*)d_in[12];
    const int*   iidx  = (const int*)d_in[13];
    float* out = (float*)d_out;

    // zero accumulators + stat slots
    k_init<<<(NUSERS * DIM / 4 + 255) / 256, 256>>>();
    // column sums of W
    k_colsum<<<1, 256>>>(wr_w);
    // fused stats + GEMM (raw outputs)
    k_gemm<<<(NUSERS + 63) / 64, 128>>>(uf,  wr_w, NUSERS, 0, 0);
    k_gemm<<<(NITEMS + 63) / 64, 128>>>(itf, wr_w, NITEMS, 2, 1);
    // epilogue: fold feature-normalization, sigmoid, gather sig-stats
    k_epi<<<(NUSERS * DIM + 255) / 256, 256>>>(wr_b, NUSERS * DIM,
                                               (double)NUSERS * NFEATS, 0, 4, 0);
    k_epi<<<(NITEMS * DIM + 255) / 256, 256>>>(wr_b, NITEMS * DIM,
                                               (double)NITEMS * NFEATS, 2, 6, 1);
    // fusion with embeddings
    k_fusion<<<(NUSERS * DIM + 255) / 256, 256>>>(uemb, NUSERS * DIM, 4, 0);
    k_fusion<<<(NITEMS * DIM + 255) / 256, 256>>>(iemb, NITEMS * DIM, 6, 1);
    // item_consumed -> g_last
    k_spmm<<<(EUI * 8 + 255) / 256, 256>>>(urows, ucols, uvals, EUI, 0, 0);
    // h1 = S @ user_fusion -> g_h1
    k_spmm<<<(ESOC * 8 + 255) / 256, 256>>>(srows, scols, svals, ESOC, 1, 1);
    // h2 = S @ h1 -> accumulate into g_last
    k_spmm<<<(ESOC * 8 + 255) / 256, 256>>>(srows, scols, svals, ESOC, 2, 0);
    // predictions
    k_pred<<<(NPAIRS * 8 + 255) / 256, 256>>>(uidx, iidx, out, out_size);
}

// round 2
// speedup vs baseline: 1.3724x; 1.3724x over previous
#include <cuda_runtime.h>
#include <math.h>

#define NUSERS 100000
#define NITEMS 50000
#define NFEATS 512
#define DIM 32
#define ESOC 3200000
#define EUI 3200000
#define NPAIRS 1000000

// ---------------- scratch (device globals; no allocs allowed) ----------------
__device__ double g_red[8];            // [0,1]=uf sum/sq [2,3]=itf [4,5]=usig [6,7]=isig
__device__ float  g_colsum[DIM];       // column sums of wr_w
__device__ float  g_user_sig[NUSERS * DIM];   // raw GEMM -> sigmoid (in place)
__device__ float  g_item_sig[NITEMS * DIM];
__device__ float  g_user_fus[NUSERS * DIM];
__device__ float  g_item_fus[NITEMS * DIM];
__device__ float  g_h1[NUSERS * DIM];
__device__ float  g_last[NUSERS * DIM];       // item_consumed + h2 accumulate here

// ---------------- init: zero accumulators ----------------
__global__ void k_init() {
    int i = blockIdx.x * blockDim.x + threadIdx.x;
    float4 z = make_float4(0.f, 0.f, 0.f, 0.f);
    const int n4 = NUSERS * DIM / 4;
    if (i < n4) {
        reinterpret_cast<float4*>(g_h1)[i]   = z;
        reinterpret_cast<float4*>(g_last)[i] = z;
    }
    if (i < 8) g_red[i] = 0.0;
}

// ---------------- column sums of W (512x32) ----------------
__global__ void k_colsum(const float* __restrict__ W) {
    __shared__ float s[8][DIM];
    int c = threadIdx.x & 31;
    int g = threadIdx.x >> 5;
    float acc = 0.f;
    for (int k = g; k < NFEATS; k += 8) acc += W[k * DIM + c];
    s[g][c] = acc;
    __syncthreads();
    if (g == 0) {
        float t = 0.f;
#pragma unroll
        for (int j = 0; j < 8; j++) t += s[j][c];
        g_colsum[c] = t;
    }
}

// ---------------- GEMM: raw = F @ W, fused feature-stats (fp32 local) ----------------
// Block: 128 threads, 64 rows x 32 cols, per-thread 4x4 register tile.
__global__ __launch_bounds__(128) void k_gemm(const float* __restrict__ F,
                                              const float* __restrict__ W,
                                              int M, int redIdx, int outSel) {
    __shared__ float sF[64][33];
    __shared__ float sW[32][36];
    float* __restrict__ out = outSel ? g_item_sig : g_user_sig;

    int t  = threadIdx.x;
    int tc = t & 7;
    int tr = t >> 3;
    int row0 = blockIdx.x * 64;

    float acc[4][4] = {};
    float lsum = 0.f, lsq = 0.f;   // fp32: each thread sums only 256 elements

    for (int kt = 0; kt < NFEATS / 32; ++kt) {
        int k0 = kt * 32;
#pragma unroll
        for (int i = 0; i < 4; ++i) {
            int fi = t + i * 128;
            int r = fi >> 3, kq = fi & 7;
            float4 v = make_float4(0.f, 0.f, 0.f, 0.f);
            int grow = row0 + r;
            if (grow < M)
                v = *reinterpret_cast<const float4*>(&F[(size_t)grow * NFEATS + k0 + kq * 4]);
            sF[r][kq * 4 + 0] = v.x; sF[r][kq * 4 + 1] = v.y;
            sF[r][kq * 4 + 2] = v.z; sF[r][kq * 4 + 3] = v.w;
            lsum += v.x + v.y + v.z + v.w;
            lsq  += v.x * v.x + v.y * v.y + v.z * v.z + v.w * v.w;
        }
#pragma unroll
        for (int i = 0; i < 2; ++i) {
            int fi = t + i * 128;
            int kr = fi >> 3, kq = fi & 7;
            float4 w = *reinterpret_cast<const float4*>(&W[(size_t)(k0 + kr) * DIM + kq * 4]);
            sW[kr][kq * 4 + 0] = w.x; sW[kr][kq * 4 + 1] = w.y;
            sW[kr][kq * 4 + 2] = w.z; sW[kr][kq * 4 + 3] = w.w;
        }
        __syncthreads();
#pragma unroll
        for (int k = 0; k < 32; ++k) {
            float4 w = *reinterpret_cast<float4*>(&sW[k][tc * 4]);
            float f0 = sF[tr * 4 + 0][k];
            float f1 = sF[tr * 4 + 1][k];
            float f2 = sF[tr * 4 + 2][k];
            float f3 = sF[tr * 4 + 3][k];
            acc[0][0] += f0 * w.x; acc[0][1] += f0 * w.y; acc[0][2] += f0 * w.z; acc[0][3] += f0 * w.w;
            acc[1][0] += f1 * w.x; acc[1][1] += f1 * w.y; acc[1][2] += f1 * w.z; acc[1][3] += f1 * w.w;
            acc[2][0] += f2 * w.x; acc[2][1] += f2 * w.y; acc[2][2] += f2 * w.z; acc[2][3] += f2 * w.w;
            acc[3][0] += f3 * w.x; acc[3][1] += f3 * w.y; acc[3][2] += f3 * w.z; acc[3][3] += f3 * w.w;
        }
        __syncthreads();
    }

    // reduce feature stats: warp shuffle (fp32 -> fp64 at block level)
#pragma unroll
    for (int o = 16; o; o >>= 1) {
        lsum += __shfl_down_sync(0xffffffffu, lsum, o);
        lsq  += __shfl_down_sync(0xffffffffu, lsq, o);
    }
    __shared__ double sred[4][2];
    int wid = t >> 5, lane = t & 31;
    if (lane == 0) { sred[wid][0] = (double)lsum; sred[wid][1] = (double)lsq; }
    __syncthreads();
    if (t == 0) {
        double a = 0.0, b = 0.0;
#pragma unroll
        for (int j = 0; j < 4; j++) { a += sred[j][0]; b += sred[j][1]; }
        atomicAdd(&g_red[redIdx], a);
        atomicAdd(&g_red[redIdx + 1], b);
    }

#pragma unroll
    for (int i = 0; i < 4; ++i) {
        int grow = row0 + tr * 4 + i;
        if (grow < M) {
            float4 o4 = make_float4(acc[i][0], acc[i][1], acc[i][2], acc[i][3]);
            *reinterpret_cast<float4*>(&out[(size_t)grow * DIM + tc * 4]) = o4;
        }
    }
}

// ---------------- epilogue: normalize-fold + sigmoid, fused sig-stats ----------------
__global__ void k_epi(const float* __restrict__ b, int n, double Nfeat,
                      int si, int so, int sel) {
    float* __restrict__ sig = sel ? g_item_sig : g_user_sig;
    double fsum = g_red[si], fsq = g_red[si + 1];
    double mean = fsum / Nfeat;
    double var  = (fsq - fsum * fsum / Nfeat) / (Nfeat - 1.0);
    float inv_s = (float)(1.0 / sqrt(var));
    float mis   = (float)mean * inv_s;

    int i = blockIdx.x * blockDim.x + threadIdx.x;
    double lsum = 0.0, lsq = 0.0;
    if (i < n) {
        int j = i & (DIM - 1);
        float x = sig[i] * inv_s + b[j] - mis * g_colsum[j];
        float v = 1.f / (1.f + expf(-x));
        sig[i] = v;
        lsum = v;
        lsq  = (double)v * v;
    }
#pragma unroll
    for (int o = 16; o; o >>= 1) {
        lsum += __shfl_down_sync(0xffffffffu, lsum, o);
        lsq  += __shfl_down_sync(0xffffffffu, lsq, o);
    }
    __shared__ double sred[8][2];
    int wid = threadIdx.x >> 5, lane = threadIdx.x & 31;
    if (lane == 0) { sred[wid][0] = lsum; sred[wid][1] = lsq; }
    __syncthreads();
    if (threadIdx.x == 0) {
        double a = 0.0, c = 0.0;
#pragma unroll
        for (int j = 0; j < 8; j++) { a += sred[j][0]; c += sred[j][1]; }
        atomicAdd(&g_red[so], a);
        atomicAdd(&g_red[so + 1], c);
    }
}

// ---------------- fusion: (sig - m)/s + embedding ----------------
__global__ void k_fusion(const float* __restrict__ emb, int n, int si, int sel) {
    const float* __restrict__ sig = sel ? g_item_sig : g_user_sig;
    float* __restrict__ fus = sel ? g_item_fus : g_user_fus;
    double s0 = g_red[si], s1 = g_red[si + 1];
    double N = (double)n;
    double mean = s0 / N;
    double var  = (s1 - s0 * s0 / N) / (N - 1.0);
    float inv = (float)(1.0 / sqrt(var));
    float m   = (float)mean;
    int i = blockIdx.x * blockDim.x + threadIdx.x;
    if (i < n) fus[i] = (sig[i] - m) * inv + emb[i];
}

// ---------------- SpMM: smem-staged edges, 8 threads/edge, v4 reductions ----------------
#define SPMM_EB 1024
__global__ __launch_bounds__(256) void k_spmm(const int* __restrict__ rows,
                                              const int* __restrict__ cols,
                                              const float* __restrict__ vals,
                                              int nE, int selX, int selOut) {
    __shared__ int   sr[SPMM_EB];
    __shared__ int   sc[SPMM_EB];
    __shared__ float sv[SPMM_EB];
    const float* __restrict__ X =
        (selX == 0) ? g_item_fus : (selX == 1) ? g_user_fus : g_h1;
    float* __restrict__ OUT = selOut ? g_h1 : g_last;

    int base = blockIdx.x * SPMM_EB;
    int n = nE - base; if (n > SPMM_EB) n = SPMM_EB;
    for (int i = threadIdx.x; i < n; i += 256) {
        sr[i] = rows[base + i];
        sc[i] = cols[base + i];
        sv[i] = vals[base + i];
    }
    __syncthreads();

    int sub = threadIdx.x & 7;
    int grp = threadIdx.x >> 3;           // 32 groups of 8
    for (int e = grp; e < n; e += 32) {
        int r = sr[e];
        int c = sc[e];
        float v = sv[e];
        float4 x = *reinterpret_cast<const float4*>(&X[(size_t)c * DIM + sub * 4]);
        float* p = &OUT[(size_t)r * DIM + sub * 4];
        asm volatile("red.global.add.v4.f32 [%0], {%1,%2,%3,%4};"
                     :: "l"(p), "f"(x.x * v), "f"(x.y * v), "f"(x.z * v), "f"(x.w * v)
                     : "memory");
    }
}

// ---------------- prediction: smem-staged indices, 8 threads/pair ----------------
__global__ __launch_bounds__(256) void k_pred(const int* __restrict__ ui,
                                              const int* __restrict__ ii,
                                              float* __restrict__ out, int out_size) {
    __shared__ int su[256];
    __shared__ int sI[256];
    int base = blockIdx.x << 8;
    int t = threadIdx.x;
    int n = NPAIRS - base; if (n > 256) n = 256;
    if (t < n) { su[t] = ui[base + t]; sI[t] = ii[base + t]; }
    __syncthreads();

    int sub = t & 7, grp = t >> 3;
    for (int p = grp; p < n; p += 32) {
        int u  = su[p];
        int it = sI[p];
        float4 a = *reinterpret_cast<const float4*>(&g_last[(size_t)u * DIM + sub * 4]);
        float4 b = *reinterpret_cast<const float4*>(&g_item_fus[(size_t)it * DIM + sub * 4]);
        float d = a.x * b.x + a.y * b.y + a.z * b.z + a.w * b.w;
#pragma unroll
        for (int o = 4; o; o >>= 1) d += __shfl_down_sync(0xffffffffu, d, o, 8);
        if (sub == 0) {
            int gp = base + p;
            if (gp < out_size) out[gp] = d;
            if (NPAIRS + gp < out_size) out[NPAIRS + gp] = 1.f / (1.f + expf(-d));
        }
    }
}

// ---------------- launch ----------------
extern "C" void kernel_launch(void* const* d_in, const int* in_sizes, int n_in,
                              void* d_out, int out_size) {
    const float* uf    = (const float*)d_in[0];
    const float* itf   = (const float*)d_in[1];
    const float* uemb  = (const float*)d_in[2];
    const float* iemb  = (const float*)d_in[3];
    const float* wr_w  = (const float*)d_in[4];
    const float* wr_b  = (const float*)d_in[5];
    const int*   srows = (const int*)d_in[6];
    const int*   scols = (const int*)d_in[7];
    const float* svals = (const float*)d_in[8];
    const int*   urows = (const int*)d_in[9];
    const int*   ucols = (const int*)d_in[10];
    const float* uvals = (const float*)d_in[11];
    const int*   uidx  = (const int*)d_in[12];
    const int*   iidx  = (const int*)d_in[13];
    float* out = (float*)d_out;

    k_init<<<(NUSERS * DIM / 4 + 255) / 256, 256>>>();
    k_colsum<<<1, 256>>>(wr_w);
    k_gemm<<<(NUSERS + 63) / 64, 128>>>(uf,  wr_w, NUSERS, 0, 0);
    k_gemm<<<(NITEMS + 63) / 64, 128>>>(itf, wr_w, NITEMS, 2, 1);
    k_epi<<<(NUSERS * DIM + 255) / 256, 256>>>(wr_b, NUSERS * DIM,
                                               (double)NUSERS * NFEATS, 0, 4, 0);
    k_epi<<<(NITEMS * DIM + 255) / 256, 256>>>(wr_b, NITEMS * DIM,
                                               (double)NITEMS * NFEATS, 2, 6, 1);
    k_fusion<<<(NUSERS * DIM + 255) / 256, 256>>>(uemb, NUSERS * DIM, 4, 0);
    k_fusion<<<(NITEMS * DIM + 255) / 256, 256>>>(iemb, NITEMS * DIM, 6, 1);
    k_spmm<<<(EUI  + SPMM_EB - 1) / SPMM_EB, 256>>>(urows, ucols, uvals, EUI, 0, 0);
    k_spmm<<<(ESOC + SPMM_EB - 1) / SPMM_EB, 256>>>(srows, scols, svals, ESOC, 1, 1);
    k_spmm<<<(ESOC + SPMM_EB - 1) / SPMM_EB, 256>>>(srows, scols, svals, ESOC, 2, 0);
    k_pred<<<(NPAIRS + 255) / 256, 256>>>(uidx, iidx, out, out_size);
}